// round 15
// baseline (speedup 1.0000x reference)
#include <cuda_runtime.h>
#include <cuda_bf16.h>
#include <stdint.h>

// ===========================================================================
// GenNCA via mma.sync.m16n8k16 bf16. R15: mask-driven pixel compaction.
// mma.sync on sm_100 is issue-rate-bound (~16cyc/SMSP) -> reduce mma count:
// dx is discarded for ~50% of pixels (mask=0). Masks are data-independent
// (threefry of step/pixel), so: scan active pixels, copy masked state
// directly, and run GEMM only on compacted active slots (tiles of 64).
// Per-pixel arithmetic identical to R8 -> rel_err canary 4.241182e-05.
// ===========================================================================
#define STEPS_ 64
#define PLANE_ (8 * 32 * 128 * 128)

__device__ float    g_xf[2][PLANE_];          // fp32 master state, NHWC
__device__ unsigned short g_xq[2][PLANE_ * 2];// operand planes [px][hi32|lo32] bf16
__device__ float    g_Mf[288 * 128];          // folded weights [k][hid]
__device__ unsigned short g_B1h[128 * 296];   // hi  [n=hid][k=288 +pad]
__device__ uint2    g_B1l[18 * 16 * 32];      // lo fragments [kk][ntile][lane]
__device__ unsigned short g_B2h[32 * 136];    // fc1 hi [o][h +pad]
__device__ unsigned short g_B2l[32 * 136];    // fc1 lo
__device__ float    g_bp[128];
__device__ unsigned g_keys[2 * STEPS_];

// ---- smem byte offsets ----
#define SAH_   0          // compacted A hi: 64 slots x 592B
#define SAL_   37888      // compacted A lo
#define SB1_   75776      // 128 x 592
#define SB2H_  151552     // 32 x 272
#define SB2L_  160256
#define SHHI_  168960     // 64 x 272
#define SHLO_  186368
#define SBIAS_ 203776     // 128 floats
#define SACT_  204288     // 1088 uint16 (act list + pad)
#define SCNT_  206464     // 8 warp sums (int)
#define SMEM_BYTES 206592

// ---------------------------------------------------------------------------
__device__ __forceinline__ uint32_t smem_u32(const void* p) {
    uint32_t a;
    asm("{ .reg .u64 t; cvta.to.shared.u64 t, %1; cvt.u32.u64 %0, t; }" : "=r"(a) : "l"(p));
    return a;
}
__device__ __forceinline__ void cp16(uint32_t dst, const void* src) {
    asm volatile("cp.async.cg.shared.global [%0], [%1], 16;" :: "r"(dst), "l"(src) : "memory");
}
#define CP_COMMIT() asm volatile("cp.async.commit_group;" ::: "memory")
#define CP_WAIT0()  asm volatile("cp.async.wait_group 0;" ::: "memory")
__device__ __forceinline__ void ldm4(uint32_t* d, uint32_t a) {
    asm volatile("ldmatrix.sync.aligned.m8n8.x4.shared.b16 {%0,%1,%2,%3}, [%4];"
                 : "=r"(d[0]), "=r"(d[1]), "=r"(d[2]), "=r"(d[3]) : "r"(a));
}
__device__ __forceinline__ void mmabf(float* c, const uint32_t* a, uint32_t b0, uint32_t b1) {
    asm volatile("mma.sync.aligned.m16n8k16.row.col.f32.bf16.bf16.f32 "
                 "{%0,%1,%2,%3}, {%4,%5,%6,%7}, {%8,%9}, {%0,%1,%2,%3};"
                 : "+f"(c[0]), "+f"(c[1]), "+f"(c[2]), "+f"(c[3])
                 : "r"(a[0]), "r"(a[1]), "r"(a[2]), "r"(a[3]), "r"(b0), "r"(b1));
}
__device__ __forceinline__ unsigned short bfhi(float v) {
    return __bfloat16_as_ushort(__float2bfloat16(v));
}
__device__ __forceinline__ unsigned short bflo(float v) {
    float h = __bfloat162float(__float2bfloat16(v));
    return __bfloat16_as_ushort(__float2bfloat16(v - h));
}
__device__ __forceinline__ uint32_t pack2(unsigned short a, unsigned short b) {
    return (uint32_t)a | ((uint32_t)b << 16);
}

// ---------------------------------------------------------------------------
__device__ __forceinline__ void threefry2x32(unsigned k0, unsigned k1,
                                             unsigned x0, unsigned x1,
                                             unsigned& o0, unsigned& o1) {
    unsigned ks2 = k0 ^ k1 ^ 0x1BD11BDAu;
#define TFR(r) { x0 += x1; x1 = __funnelshift_l(x1, x1, (r)); x1 ^= x0; }
    x0 += k0; x1 += k1;
    TFR(13) TFR(15) TFR(26) TFR(6)  x0 += k1;  x1 += ks2 + 1u;
    TFR(17) TFR(29) TFR(16) TFR(24) x0 += ks2; x1 += k0 + 2u;
    TFR(13) TFR(15) TFR(26) TFR(6)  x0 += k0;  x1 += k1 + 3u;
    TFR(17) TFR(29) TFR(16) TFR(24) x0 += k1;  x1 += ks2 + 4u;
    TFR(13) TFR(15) TFR(26) TFR(6)  x0 += ks2; x1 += k0 + 5u;
#undef TFR
    o0 = x0; o1 = x1;
}
__device__ __forceinline__ int active_for(unsigned k0, unsigned k1, unsigned idx) {
    unsigned o0, o1;
    threefry2x32(k0, k1, 0u, idx, o0, o1);
    unsigned bits = o0 ^ o1;
    float u = __uint_as_float((bits >> 9) | 0x3f800000u) - 1.0f;
    return (u > 0.5f) ? 1 : 0;
}

// ---------------------------------------------------------------------------
__global__ void prep1(const float* __restrict__ fc0w, const float* __restrict__ fc0b,
                      const float* __restrict__ p0w, const float* __restrict__ p0b,
                      const float* __restrict__ p1w, const float* __restrict__ p1b) {
    int bid = blockIdx.x, h = threadIdx.x;
    if (bid < 288) {
        int tap = bid >> 5, c = bid & 31;
        float acc = (tap == 4) ? fc0w[h * 96 + c] : 0.0f;
        const float* w0 = &p0w[bid * 32];
        const float* w1 = &p1w[bid * 32];
        const float* f1 = &fc0w[h * 96 + 32];
        const float* f2 = &fc0w[h * 96 + 64];
#pragma unroll
        for (int o = 0; o < 32; o++) acc += w0[o] * f1[o] + w1[o] * f2[o];
        g_Mf[bid * 128 + h] = acc;
    } else {
        float acc = fc0b[h];
        const float* f1 = &fc0w[h * 96 + 32];
        const float* f2 = &fc0w[h * 96 + 64];
#pragma unroll
        for (int o = 0; o < 32; o++) acc += p0b[o] * f1[o] + p1b[o] * f2[o];
        g_bp[h] = acc;
        if (h == 0)
            for (unsigned s = 0; s < STEPS_; s++) {
                unsigned a, b;
                threefry2x32(0u, 42u, 0u, s, a, b);
                g_keys[2 * s] = a; g_keys[2 * s + 1] = b;
            }
    }
}

__global__ void prep2(const float* __restrict__ fc1w) {
    int tid = blockIdx.x * 256 + threadIdx.x;
    if (tid < 36864) {                 // B1 hi: [n][k]
        int n = tid / 288, k = tid % 288;
        g_B1h[n * 296 + k] = bfhi(g_Mf[k * 128 + n]);
    } else if (tid < 46080) {          // B1 lo fragments
        int j = tid - 36864;
        int l = j & 31, ntile = (j >> 5) & 15, kk = j >> 9;
        int n = ntile * 8 + (l >> 2), k0 = kk * 16 + 2 * (l & 3);
        g_B1l[j] = make_uint2(
            pack2(bflo(g_Mf[k0 * 128 + n]),       bflo(g_Mf[(k0 + 1) * 128 + n])),
            pack2(bflo(g_Mf[(k0 + 8) * 128 + n]), bflo(g_Mf[(k0 + 9) * 128 + n])));
    } else if (tid < 50176) {          // B2: [o][h]
        int j = tid - 46080;
        int o = j >> 7, h = j & 127;
        float v = fc1w[j];
        g_B2h[o * 136 + h] = bfhi(v);
        g_B2l[o * 136 + h] = bflo(v);
    }
}

__global__ void init_state(const float* __restrict__ x, const float* __restrict__ xvec,
                           const float* __restrict__ bptw, const float* __restrict__ bptb) {
    int tid = blockIdx.x * blockDim.x + threadIdx.x;
    if (tid >= PLANE_) return;
    int c = tid & 31, b = tid >> 19;
    float v;
    if (c >= 26) {
        int e = c - 26;
        v = bptw[b * 6 + e] * xvec[b * 6 + e] + bptb[b * 6 + e];
    } else v = x[tid];
    g_xf[0][tid] = v;
    int p = tid >> 5;
    g_xq[0][p * 64 + c] = bfhi(v);
    g_xq[0][p * 64 + 32 + c] = bflo(v);
}

__global__ void final_out(float* __restrict__ out) {
    int tid = blockIdx.x * blockDim.x + threadIdx.x;
    if (tid >= PLANE_) return;
    out[tid] = g_xf[0][tid];
}

// ---------------------------------------------------------------------------
// Step kernel: block = (8-row group, batch), 256 threads (8 warps).
// Prologue: masks -> prefix scan -> act[] list; masked px copied directly.
// Tiles of 64 compacted slots: A gathered (im2col) via cp.async from gmem;
// GEMM1 (warp = 16 slot x 64 hid), epi1 -> sH, GEMM2 (16 slot x 16 out),
// epi2 scatters dx+residual to the slot's (row,px).
// ---------------------------------------------------------------------------
__global__ void __launch_bounds__(256, 1) nca_step(int s) {
    extern __shared__ char smem[];
    const uint32_t sb = smem_u32(smem);
    float* sbias = (float*)(smem + SBIAS_);
    unsigned short* sact = (unsigned short*)(smem + SACT_);
    int* scnt = (int*)(smem + SCNT_);

    const int t = threadIdx.x, l = t & 31, wid = t >> 5;
    const int b = blockIdx.y, r0 = blockIdx.x * 8;
    const int mg = wid & 3, ng = wid >> 2;     // GEMM1: 16 slot-rows x 64 hid
    const int mg2 = wid >> 1, ng2 = wid & 1;   // GEMM2: 16 slot-rows x 16 out

    const unsigned short* __restrict__ xq_in = g_xq[s & 1];
    unsigned short*       __restrict__ xq_out = g_xq[(s & 1) ^ 1];
    const float* __restrict__ xf_in = g_xf[s & 1];
    float*       __restrict__ xf_out = g_xf[(s & 1) ^ 1];

    // resident weights (group committed; waited with tile-0 gather)
    for (int u = t; u < 4736; u += 256) cp16(sb + SB1_ + u * 16, (const char*)g_B1h + u * 16);
    for (int u = t; u < 544; u += 256)  cp16(sb + SB2H_ + u * 16, (const char*)g_B2h + u * 16);
    for (int u = t; u < 544; u += 256)  cp16(sb + SB2L_ + u * 16, (const char*)g_B2l + u * 16);
    CP_COMMIT();
    if (t < 128) sbias[t] = g_bp[t];

    const unsigned key0 = g_keys[2 * s], key1 = g_keys[2 * s + 1];
    const unsigned base0 = (unsigned)(((b << 7) + r0) << 7);

    // ---- masks for this block's 1024 pixels; warp+block prefix scan ----
    int u4 = t << 2;
    int mk[4], loc = 0;
#pragma unroll
    for (int k = 0; k < 4; k++) {
        mk[k] = active_for(key0, key1, base0 + (unsigned)(u4 + k));
        loc += mk[k];
    }
    int ws = loc;
#pragma unroll
    for (int d = 1; d < 32; d <<= 1) {
        int v = __shfl_up_sync(0xffffffffu, ws, d);
        if (l >= d) ws += v;
    }
    if (l == 31) scnt[wid] = ws;
    __syncthreads();
    int A = 0, wbase = 0;
#pragma unroll
    for (int w = 0; w < 8; w++) {
        int v = scnt[w];
        if (w < wid) wbase += v;
        A += v;
    }
    int base = wbase + ws - loc;

    // write act list; copy masked pixels' state directly (disjoint from scatter)
#pragma unroll
    for (int k = 0; k < 4; k++) {
        int uu = u4 + k;
        if (mk[k]) {
            sact[base++] = (unsigned short)uu;
        } else {
            size_t pb = (size_t)(base0 + (unsigned)uu);
            const float4* s1 = (const float4*)(xf_in + pb * 32);
            float4* d1 = (float4*)(xf_out + pb * 32);
            const uint4* s2 = (const uint4*)((const char*)xq_in + pb * 128);
            uint4* d2 = (uint4*)((char*)xq_out + pb * 128);
#pragma unroll
            for (int j = 0; j < 8; j++) d1[j] = s1[j];
#pragma unroll
            for (int j = 0; j < 8; j++) d2[j] = s2[j];
        }
    }
    __syncthreads();
    const int ntile = (A + 63) >> 6;
    if (A > 0 && t < ntile * 64 - A) sact[A + t] = sact[0];
    __syncthreads();

    // ---- im2col gather of one 64-slot tile into sAc (cp.async) ----
    auto gather = [&](int tt) {
        int i = t >> 2, q = t & 3;
        unsigned uu = sact[tt * 64 + i];
        int rr = uu >> 7, px = uu & 127;
        int rgl = r0 + rr;
#pragma unroll
        for (int j = 0; j < 18; j++) {
            int ch = q * 18 + j;
            int ta = ch >> 3, part = ch & 7;
            int dy = ta / 3, dxp = ta - dy * 3;
            int rs = rgl - 1 + dy; rs = rs < 0 ? 1 : (rs > 127 ? 126 : rs);
            int ps = px - 1 + dxp; ps = ps < 0 ? 1 : (ps > 127 ? 126 : ps);
            const char* src = (const char*)xq_in
                + ((size_t)((((b << 7) + rs) << 7) + ps)) * 128
                + (part & 3) * 16 + ((part >> 2) << 6);
            uint32_t dst = sb + (part < 4 ? SAH_ : SAL_)
                + (uint32_t)i * 592 + (uint32_t)ta * 64 + (uint32_t)(part & 3) * 16;
            cp16(dst, src);
        }
        CP_COMMIT();
    };
    if (ntile > 0) gather(0);

    // per-lane bases
    const uint32_t aoffc = (uint32_t)(l & 15) * 592 + (uint32_t)(l >> 4) * 16;
    const uint32_t abase = sb + SAH_ + (uint32_t)(mg * 16) * 592 + aoffc;
    const uint32_t b1off = sb + SB1_ + (uint32_t)(ng * 64 + ((l >> 4) << 3) + (l & 7)) * 592
                         + (uint32_t)((l >> 3) & 1) * 16;
    const uint32_t hoff  = sb + SHHI_ + (uint32_t)(mg2 * 16 + (l & 15)) * 272 + (uint32_t)(l >> 4) * 16;
    const uint32_t b2off = sb + SB2H_ + (uint32_t)(ng2 * 16 + ((l >> 4) << 3) + (l & 7)) * 272
                         + (uint32_t)((l >> 3) & 1) * 16;

    for (int tile = 0; tile < ntile; tile++) {
        CP_WAIT0();
        __syncthreads();    // sAc(tile) ready; all warps finished previous tile

        // ========== GEMM1: 64 slots x 128 hid, K=288 ==========
        float c1[8][4];
#pragma unroll
        for (int nt = 0; nt < 8; nt++)
#pragma unroll
            for (int i = 0; i < 4; i++) c1[nt][i] = 0.0f;

#pragma unroll 1
        for (int kk = 0; kk < 18; kk++) {
            uint32_t ah[4], al[4], bh[4][4];
            uint2 bl[8];
            ldm4(ah, abase + (uint32_t)kk * 32);
            ldm4(al, abase + (SAL_ - SAH_) + (uint32_t)kk * 32);
#pragma unroll
            for (int j = 0; j < 4; j++)
                ldm4(bh[j], b1off + (uint32_t)j * (16 * 592) + (uint32_t)kk * 32);
#pragma unroll
            for (int nt = 0; nt < 8; nt++)
                bl[nt] = __ldg(&g_B1l[(kk * 16 + ng * 8 + nt) * 32 + l]);
            // term1: hi*hi
#pragma unroll
            for (int nt = 0; nt < 8; nt++)
                mmabf(c1[nt], ah, bh[nt >> 1][(nt & 1) * 2], bh[nt >> 1][(nt & 1) * 2 + 1]);
            // term2: lo_a*hi_b
#pragma unroll
            for (int nt = 0; nt < 8; nt++)
                mmabf(c1[nt], al, bh[nt >> 1][(nt & 1) * 2], bh[nt >> 1][(nt & 1) * 2 + 1]);
            // term3: hi_a*lo_b
#pragma unroll
            for (int nt = 0; nt < 8; nt++)
                mmabf(c1[nt], ah, bl[nt].x, bl[nt].y);
        }
        __syncthreads();    // all warps done reading sAc
        if (tile + 1 < ntile) gather(tile + 1);

        // ---- epilogue1: bias+relu, split -> sH hi/lo ----
        {
            int px_s = mg * 16 + (l >> 2);
#pragma unroll
            for (int nt = 0; nt < 8; nt++) {
                int o = ng * 64 + nt * 8 + ((l & 3) << 1);
                float b0 = sbias[o], b1 = sbias[o + 1];
                float v0 = fmaxf(c1[nt][0] + b0, 0.f), v1 = fmaxf(c1[nt][1] + b1, 0.f);
                float v2 = fmaxf(c1[nt][2] + b0, 0.f), v3 = fmaxf(c1[nt][3] + b1, 0.f);
                *(uint32_t*)(smem + SHHI_ + px_s * 272 + o * 2) = pack2(bfhi(v0), bfhi(v1));
                *(uint32_t*)(smem + SHHI_ + (px_s + 8) * 272 + o * 2) = pack2(bfhi(v2), bfhi(v3));
                *(uint32_t*)(smem + SHLO_ + px_s * 272 + o * 2) = pack2(bflo(v0), bflo(v1));
                *(uint32_t*)(smem + SHLO_ + (px_s + 8) * 272 + o * 2) = pack2(bflo(v2), bflo(v3));
            }
        }
        __syncthreads();    // sH ready

        // ========== GEMM2: 64 slots x 32 out, K=128 ==========
        float c2[2][4];
#pragma unroll
        for (int nt = 0; nt < 2; nt++)
#pragma unroll
            for (int i = 0; i < 4; i++) c2[nt][i] = 0.0f;
#pragma unroll 1
        for (int kk = 0; kk < 8; kk++) {
            uint32_t ah[4], al[4], bh[4], blr[4];
            ldm4(ah, hoff + (uint32_t)kk * 32);
            ldm4(al, hoff + (SHLO_ - SHHI_) + (uint32_t)kk * 32);
            ldm4(bh, b2off + (uint32_t)kk * 32);
            ldm4(blr, b2off + (SB2L_ - SB2H_) + (uint32_t)kk * 32);
#pragma unroll
            for (int nt = 0; nt < 2; nt++) {
                mmabf(c2[nt], ah, bh[nt * 2], bh[nt * 2 + 1]);
                mmabf(c2[nt], al, bh[nt * 2], bh[nt * 2 + 1]);
                mmabf(c2[nt], ah, blr[nt * 2], blr[nt * 2 + 1]);
            }
        }

        // ---- epilogue2: scatter dx + residual to (row,px) of each slot ----
        {
            int sl0 = mg2 * 16 + (l >> 2);
            uint32_t* xo = (uint32_t*)xq_out;
#pragma unroll
            for (int half = 0; half < 2; half++) {
                int sl = sl0 + half * 8;
                int gslot = tile * 64 + sl;
                if (gslot < A) {
                    unsigned uu = sact[gslot];
                    uint32_t pb = base0 + uu;
#pragma unroll
                    for (int nt = 0; nt < 2; nt++) {
                        int o = ng2 * 16 + nt * 8 + ((l & 3) << 1);
                        float2 x0 = *(const float2*)&xf_in[(size_t)pb * 32 + o];
                        float n0 = x0.x + c2[nt][half * 2 + 0];
                        float n1 = x0.y + c2[nt][half * 2 + 1];
                        *(float2*)&xf_out[(size_t)pb * 32 + o] = make_float2(n0, n1);
                        uint32_t gi = (pb << 5) + (uint32_t)(o >> 1);
                        xo[gi]      = pack2(bfhi(n0), bfhi(n1));
                        xo[gi + 16] = pack2(bflo(n0), bflo(n1));
                    }
                }
            }
        }
    }
}

// ---------------------------------------------------------------------------
extern "C" void kernel_launch(void* const* d_in, const int* in_sizes, int n_in,
                              void* d_out, int out_size) {
    const float* x    = (const float*)d_in[0];
    const float* xvec = (const float*)d_in[1];
    const float* fc0w = (const float*)d_in[2];
    const float* fc0b = (const float*)d_in[3];
    const float* fc1w = (const float*)d_in[4];
    const float* p0w  = (const float*)d_in[5];
    const float* p0b  = (const float*)d_in[6];
    const float* p1w  = (const float*)d_in[7];
    const float* p1b  = (const float*)d_in[8];
    const float* bptw = (const float*)d_in[9];
    const float* bptb = (const float*)d_in[10];

    cudaFuncSetAttribute(nca_step, cudaFuncAttributeMaxDynamicSharedMemorySize, SMEM_BYTES);

    prep1<<<289, 128>>>(fc0w, fc0b, p0w, p0b, p1w, p1b);
    prep2<<<196, 256>>>(fc1w);
    init_state<<<PLANE_ / 256, 256>>>(x, xvec, bptw, bptb);
    for (int s = 0; s < STEPS_; s++)
        nca_step<<<dim3(16, 8), 256, SMEM_BYTES>>>(s);
    final_out<<<PLANE_ / 256, 256>>>((float*)d_out);
}

// round 16
// speedup vs baseline: 1.1887x; 1.1887x over previous
#include <cuda_runtime.h>
#include <cuda_bf16.h>
#include <stdint.h>

// ===========================================================================
// GenNCA via mma.sync.m16n8k16 bf16. R16 = R15 (mask compaction, canary-
// exact) with COALESCED data movement:
//  - gather: 8 lanes fetch the 8x16B chunks of one (slot,tap) pixel ->
//    contiguous 128B per 8-lane group (was 4 threads x different pixels)
//  - masked-copy: smem bitmap + cooperative 8-lanes-per-pixel 128B copies
// ===========================================================================
#define STEPS_ 64
#define PLANE_ (8 * 32 * 128 * 128)

__device__ float    g_xf[2][PLANE_];          // fp32 master state, NHWC
__device__ unsigned short g_xq[2][PLANE_ * 2];// operand planes [px][hi32|lo32] bf16
__device__ float    g_Mf[288 * 128];          // folded weights [k][hid]
__device__ unsigned short g_B1h[128 * 296];   // hi  [n=hid][k=288 +pad]
__device__ uint2    g_B1l[18 * 16 * 32];      // lo fragments [kk][ntile][lane]
__device__ unsigned short g_B2h[32 * 136];    // fc1 hi [o][h +pad]
__device__ unsigned short g_B2l[32 * 136];    // fc1 lo
__device__ float    g_bp[128];
__device__ unsigned g_keys[2 * STEPS_];

// ---- smem byte offsets ----
#define SAH_   0          // compacted A hi: 64 slots x 592B
#define SAL_   37888      // compacted A lo
#define SB1_   75776      // 128 x 592
#define SB2H_  151552     // 32 x 272
#define SB2L_  160256
#define SHHI_  168960     // 64 x 272
#define SHLO_  186368
#define SBIAS_ 203776     // 128 floats
#define SACT_  204288     // 1088 uint16
#define SCNT_  206464     // 8 ints
#define SMSK_  206496     // 1024 bytes mask bitmap
#define SMEM_BYTES 207520

// ---------------------------------------------------------------------------
__device__ __forceinline__ uint32_t smem_u32(const void* p) {
    uint32_t a;
    asm("{ .reg .u64 t; cvta.to.shared.u64 t, %1; cvt.u32.u64 %0, t; }" : "=r"(a) : "l"(p));
    return a;
}
__device__ __forceinline__ void cp16(uint32_t dst, const void* src) {
    asm volatile("cp.async.cg.shared.global [%0], [%1], 16;" :: "r"(dst), "l"(src) : "memory");
}
#define CP_COMMIT() asm volatile("cp.async.commit_group;" ::: "memory")
#define CP_WAIT0()  asm volatile("cp.async.wait_group 0;" ::: "memory")
__device__ __forceinline__ void ldm4(uint32_t* d, uint32_t a) {
    asm volatile("ldmatrix.sync.aligned.m8n8.x4.shared.b16 {%0,%1,%2,%3}, [%4];"
                 : "=r"(d[0]), "=r"(d[1]), "=r"(d[2]), "=r"(d[3]) : "r"(a));
}
__device__ __forceinline__ void mmabf(float* c, const uint32_t* a, uint32_t b0, uint32_t b1) {
    asm volatile("mma.sync.aligned.m16n8k16.row.col.f32.bf16.bf16.f32 "
                 "{%0,%1,%2,%3}, {%4,%5,%6,%7}, {%8,%9}, {%0,%1,%2,%3};"
                 : "+f"(c[0]), "+f"(c[1]), "+f"(c[2]), "+f"(c[3])
                 : "r"(a[0]), "r"(a[1]), "r"(a[2]), "r"(a[3]), "r"(b0), "r"(b1));
}
__device__ __forceinline__ unsigned short bfhi(float v) {
    return __bfloat16_as_ushort(__float2bfloat16(v));
}
__device__ __forceinline__ unsigned short bflo(float v) {
    float h = __bfloat162float(__float2bfloat16(v));
    return __bfloat16_as_ushort(__float2bfloat16(v - h));
}
__device__ __forceinline__ uint32_t pack2(unsigned short a, unsigned short b) {
    return (uint32_t)a | ((uint32_t)b << 16);
}

// ---------------------------------------------------------------------------
__device__ __forceinline__ void threefry2x32(unsigned k0, unsigned k1,
                                             unsigned x0, unsigned x1,
                                             unsigned& o0, unsigned& o1) {
    unsigned ks2 = k0 ^ k1 ^ 0x1BD11BDAu;
#define TFR(r) { x0 += x1; x1 = __funnelshift_l(x1, x1, (r)); x1 ^= x0; }
    x0 += k0; x1 += k1;
    TFR(13) TFR(15) TFR(26) TFR(6)  x0 += k1;  x1 += ks2 + 1u;
    TFR(17) TFR(29) TFR(16) TFR(24) x0 += ks2; x1 += k0 + 2u;
    TFR(13) TFR(15) TFR(26) TFR(6)  x0 += k0;  x1 += k1 + 3u;
    TFR(17) TFR(29) TFR(16) TFR(24) x0 += k1;  x1 += ks2 + 4u;
    TFR(13) TFR(15) TFR(26) TFR(6)  x0 += ks2; x1 += k0 + 5u;
#undef TFR
    o0 = x0; o1 = x1;
}
__device__ __forceinline__ int active_for(unsigned k0, unsigned k1, unsigned idx) {
    unsigned o0, o1;
    threefry2x32(k0, k1, 0u, idx, o0, o1);
    unsigned bits = o0 ^ o1;
    float u = __uint_as_float((bits >> 9) | 0x3f800000u) - 1.0f;
    return (u > 0.5f) ? 1 : 0;
}

// ---------------------------------------------------------------------------
__global__ void prep1(const float* __restrict__ fc0w, const float* __restrict__ fc0b,
                      const float* __restrict__ p0w, const float* __restrict__ p0b,
                      const float* __restrict__ p1w, const float* __restrict__ p1b) {
    int bid = blockIdx.x, h = threadIdx.x;
    if (bid < 288) {
        int tap = bid >> 5, c = bid & 31;
        float acc = (tap == 4) ? fc0w[h * 96 + c] : 0.0f;
        const float* w0 = &p0w[bid * 32];
        const float* w1 = &p1w[bid * 32];
        const float* f1 = &fc0w[h * 96 + 32];
        const float* f2 = &fc0w[h * 96 + 64];
#pragma unroll
        for (int o = 0; o < 32; o++) acc += w0[o] * f1[o] + w1[o] * f2[o];
        g_Mf[bid * 128 + h] = acc;
    } else {
        float acc = fc0b[h];
        const float* f1 = &fc0w[h * 96 + 32];
        const float* f2 = &fc0w[h * 96 + 64];
#pragma unroll
        for (int o = 0; o < 32; o++) acc += p0b[o] * f1[o] + p1b[o] * f2[o];
        g_bp[h] = acc;
        if (h == 0)
            for (unsigned s = 0; s < STEPS_; s++) {
                unsigned a, b;
                threefry2x32(0u, 42u, 0u, s, a, b);
                g_keys[2 * s] = a; g_keys[2 * s + 1] = b;
            }
    }
}

__global__ void prep2(const float* __restrict__ fc1w) {
    int tid = blockIdx.x * 256 + threadIdx.x;
    if (tid < 36864) {                 // B1 hi: [n][k]
        int n = tid / 288, k = tid % 288;
        g_B1h[n * 296 + k] = bfhi(g_Mf[k * 128 + n]);
    } else if (tid < 46080) {          // B1 lo fragments
        int j = tid - 36864;
        int l = j & 31, ntile = (j >> 5) & 15, kk = j >> 9;
        int n = ntile * 8 + (l >> 2), k0 = kk * 16 + 2 * (l & 3);
        g_B1l[j] = make_uint2(
            pack2(bflo(g_Mf[k0 * 128 + n]),       bflo(g_Mf[(k0 + 1) * 128 + n])),
            pack2(bflo(g_Mf[(k0 + 8) * 128 + n]), bflo(g_Mf[(k0 + 9) * 128 + n])));
    } else if (tid < 50176) {          // B2: [o][h]
        int j = tid - 46080;
        int o = j >> 7, h = j & 127;
        float v = fc1w[j];
        g_B2h[o * 136 + h] = bfhi(v);
        g_B2l[o * 136 + h] = bflo(v);
    }
}

__global__ void init_state(const float* __restrict__ x, const float* __restrict__ xvec,
                           const float* __restrict__ bptw, const float* __restrict__ bptb) {
    int tid = blockIdx.x * blockDim.x + threadIdx.x;
    if (tid >= PLANE_) return;
    int c = tid & 31, b = tid >> 19;
    float v;
    if (c >= 26) {
        int e = c - 26;
        v = bptw[b * 6 + e] * xvec[b * 6 + e] + bptb[b * 6 + e];
    } else v = x[tid];
    g_xf[0][tid] = v;
    int p = tid >> 5;
    g_xq[0][p * 64 + c] = bfhi(v);
    g_xq[0][p * 64 + 32 + c] = bflo(v);
}

__global__ void final_out(float* __restrict__ out) {
    int tid = blockIdx.x * blockDim.x + threadIdx.x;
    if (tid >= PLANE_) return;
    out[tid] = g_xf[0][tid];
}

// ---------------------------------------------------------------------------
// Step kernel: block = (8-row group, batch), 256 threads (8 warps).
// ---------------------------------------------------------------------------
__global__ void __launch_bounds__(256, 1) nca_step(int s) {
    extern __shared__ char smem[];
    const uint32_t sb = smem_u32(smem);
    float* sbias = (float*)(smem + SBIAS_);
    unsigned short* sact = (unsigned short*)(smem + SACT_);
    int* scnt = (int*)(smem + SCNT_);
    unsigned char* smsk = (unsigned char*)(smem + SMSK_);

    const int t = threadIdx.x, l = t & 31, wid = t >> 5;
    const int b = blockIdx.y, r0 = blockIdx.x * 8;
    const int mg = wid & 3, ng = wid >> 2;     // GEMM1: 16 slot-rows x 64 hid
    const int mg2 = wid >> 1, ng2 = wid & 1;   // GEMM2: 16 slot-rows x 16 out

    const unsigned short* __restrict__ xq_in = g_xq[s & 1];
    unsigned short*       __restrict__ xq_out = g_xq[(s & 1) ^ 1];
    const float* __restrict__ xf_in = g_xf[s & 1];
    float*       __restrict__ xf_out = g_xf[(s & 1) ^ 1];

    // resident weights
    for (int u = t; u < 4736; u += 256) cp16(sb + SB1_ + u * 16, (const char*)g_B1h + u * 16);
    for (int u = t; u < 544; u += 256)  cp16(sb + SB2H_ + u * 16, (const char*)g_B2h + u * 16);
    for (int u = t; u < 544; u += 256)  cp16(sb + SB2L_ + u * 16, (const char*)g_B2l + u * 16);
    CP_COMMIT();
    if (t < 128) sbias[t] = g_bp[t];

    const unsigned key0 = g_keys[2 * s], key1 = g_keys[2 * s + 1];
    const unsigned base0 = (unsigned)(((b << 7) + r0) << 7);

    // ---- masks for this block's 1024 pixels; warp+block prefix scan ----
    int u4 = t << 2;
    int mk[4], loc = 0;
#pragma unroll
    for (int k = 0; k < 4; k++) {
        mk[k] = active_for(key0, key1, base0 + (unsigned)(u4 + k));
        smsk[u4 + k] = (unsigned char)mk[k];
        loc += mk[k];
    }
    int ws = loc;
#pragma unroll
    for (int d = 1; d < 32; d <<= 1) {
        int v = __shfl_up_sync(0xffffffffu, ws, d);
        if (l >= d) ws += v;
    }
    if (l == 31) scnt[wid] = ws;
    __syncthreads();
    int A = 0, wbase = 0;
#pragma unroll
    for (int w = 0; w < 8; w++) {
        int v = scnt[w];
        if (w < wid) wbase += v;
        A += v;
    }
    int base = wbase + ws - loc;
#pragma unroll
    for (int k = 0; k < 4; k++)
        if (mk[k]) sact[base++] = (unsigned short)(u4 + k);
    __syncthreads();
    const int ntile = (A + 63) >> 6;
    if (A > 0 && t < ntile * 64 - A) sact[A + t] = sact[0];
    __syncthreads();

    // ---- im2col gather: 8 lanes load one (slot,tap) pixel's 128B ----
    auto gather = [&](int tt) {
#pragma unroll
        for (int it = 0; it < 18; it++) {
            int g = wid * 72 + it * 4 + (l >> 3);     // 0..575 = slot*9+tap
            int slot = g / 9, tap = g - slot * 9;
            unsigned uu = sact[tt * 64 + slot];
            int rr = (int)(uu >> 7), px = (int)(uu & 127);
            int dy = tap / 3, dxp = tap - dy * 3;
            int rs = r0 + rr - 1 + dy; rs = rs < 0 ? 1 : (rs > 127 ? 126 : rs);
            int ps = px - 1 + dxp;     ps = ps < 0 ? 1 : (ps > 127 ? 126 : ps);
            int c = l & 7;
            const char* src = (const char*)xq_in
                + ((size_t)((((b << 7) + rs) << 7) + ps)) * 128 + c * 16;
            uint32_t dst = sb + (c < 4 ? SAH_ : SAL_)
                + (uint32_t)slot * 592 + (uint32_t)tap * 64 + (uint32_t)(c & 3) * 16;
            cp16(dst, src);
        }
        CP_COMMIT();
    };
    if (ntile > 0) gather(0);

    // ---- masked-pixel copy: cooperative, 8 lanes per pixel (coalesced) ----
    for (int bu = 0; bu < 1024; bu += 32) {
        int pxi = bu + (t >> 3);
        if (!smsk[pxi]) {
            size_t pb = (size_t)(base0 + (unsigned)pxi);
            int c = t & 7;
            uint4 v1 = *(const uint4*)((const char*)xq_in + pb * 128 + c * 16);
            *(uint4*)((char*)xq_out + pb * 128 + c * 16) = v1;
            float4 v2 = *(const float4*)(xf_in + pb * 32 + c * 4);
            *(float4*)(xf_out + pb * 32 + c * 4) = v2;
        }
    }

    // per-lane bases
    const uint32_t aoffc = (uint32_t)(l & 15) * 592 + (uint32_t)(l >> 4) * 16;
    const uint32_t abase = sb + SAH_ + (uint32_t)(mg * 16) * 592 + aoffc;
    const uint32_t b1off = sb + SB1_ + (uint32_t)(ng * 64 + ((l >> 4) << 3) + (l & 7)) * 592
                         + (uint32_t)((l >> 3) & 1) * 16;
    const uint32_t hoff  = sb + SHHI_ + (uint32_t)(mg2 * 16 + (l & 15)) * 272 + (uint32_t)(l >> 4) * 16;
    const uint32_t b2off = sb + SB2H_ + (uint32_t)(ng2 * 16 + ((l >> 4) << 3) + (l & 7)) * 272
                         + (uint32_t)((l >> 3) & 1) * 16;

    for (int tile = 0; tile < ntile; tile++) {
        CP_WAIT0();
        __syncthreads();    // sAc(tile) ready; all warps finished previous tile

        // ========== GEMM1: 64 slots x 128 hid, K=288 ==========
        float c1[8][4];
#pragma unroll
        for (int nt = 0; nt < 8; nt++)
#pragma unroll
            for (int i = 0; i < 4; i++) c1[nt][i] = 0.0f;

#pragma unroll 1
        for (int kk = 0; kk < 18; kk++) {
            uint32_t ah[4], al[4], bh[4][4];
            uint2 bl[8];
            ldm4(ah, abase + (uint32_t)kk * 32);
            ldm4(al, abase + (SAL_ - SAH_) + (uint32_t)kk * 32);
#pragma unroll
            for (int j = 0; j < 4; j++)
                ldm4(bh[j], b1off + (uint32_t)j * (16 * 592) + (uint32_t)kk * 32);
#pragma unroll
            for (int nt = 0; nt < 8; nt++)
                bl[nt] = __ldg(&g_B1l[(kk * 16 + ng * 8 + nt) * 32 + l]);
            // term1: hi*hi
#pragma unroll
            for (int nt = 0; nt < 8; nt++)
                mmabf(c1[nt], ah, bh[nt >> 1][(nt & 1) * 2], bh[nt >> 1][(nt & 1) * 2 + 1]);
            // term2: lo_a*hi_b
#pragma unroll
            for (int nt = 0; nt < 8; nt++)
                mmabf(c1[nt], al, bh[nt >> 1][(nt & 1) * 2], bh[nt >> 1][(nt & 1) * 2 + 1]);
            // term3: hi_a*lo_b
#pragma unroll
            for (int nt = 0; nt < 8; nt++)
                mmabf(c1[nt], ah, bl[nt].x, bl[nt].y);
        }
        __syncthreads();    // all warps done reading sAc
        if (tile + 1 < ntile) gather(tile + 1);

        // ---- epilogue1: bias+relu, split -> sH hi/lo ----
        {
            int px_s = mg * 16 + (l >> 2);
#pragma unroll
            for (int nt = 0; nt < 8; nt++) {
                int o = ng * 64 + nt * 8 + ((l & 3) << 1);
                float b0 = sbias[o], b1 = sbias[o + 1];
                float v0 = fmaxf(c1[nt][0] + b0, 0.f), v1 = fmaxf(c1[nt][1] + b1, 0.f);
                float v2 = fmaxf(c1[nt][2] + b0, 0.f), v3 = fmaxf(c1[nt][3] + b1, 0.f);
                *(uint32_t*)(smem + SHHI_ + px_s * 272 + o * 2) = pack2(bfhi(v0), bfhi(v1));
                *(uint32_t*)(smem + SHHI_ + (px_s + 8) * 272 + o * 2) = pack2(bfhi(v2), bfhi(v3));
                *(uint32_t*)(smem + SHLO_ + px_s * 272 + o * 2) = pack2(bflo(v0), bflo(v1));
                *(uint32_t*)(smem + SHLO_ + (px_s + 8) * 272 + o * 2) = pack2(bflo(v2), bflo(v3));
            }
        }
        __syncthreads();    // sH ready

        // ========== GEMM2: 64 slots x 32 out, K=128 ==========
        float c2[2][4];
#pragma unroll
        for (int nt = 0; nt < 2; nt++)
#pragma unroll
            for (int i = 0; i < 4; i++) c2[nt][i] = 0.0f;
#pragma unroll 1
        for (int kk = 0; kk < 8; kk++) {
            uint32_t ah[4], al[4], bh[4], blr[4];
            ldm4(ah, hoff + (uint32_t)kk * 32);
            ldm4(al, hoff + (SHLO_ - SHHI_) + (uint32_t)kk * 32);
            ldm4(bh, b2off + (uint32_t)kk * 32);
            ldm4(blr, b2off + (SB2L_ - SB2H_) + (uint32_t)kk * 32);
#pragma unroll
            for (int nt = 0; nt < 2; nt++) {
                mmabf(c2[nt], ah, bh[nt * 2], bh[nt * 2 + 1]);
                mmabf(c2[nt], al, bh[nt * 2], bh[nt * 2 + 1]);
                mmabf(c2[nt], ah, blr[nt * 2], blr[nt * 2 + 1]);
            }
        }

        // ---- epilogue2: scatter dx + residual to (row,px) of each slot ----
        {
            int sl0 = mg2 * 16 + (l >> 2);
            uint32_t* xo = (uint32_t*)xq_out;
#pragma unroll
            for (int half = 0; half < 2; half++) {
                int sl = sl0 + half * 8;
                int gslot = tile * 64 + sl;
                if (gslot < A) {
                    unsigned uu = sact[gslot];
                    uint32_t pb = base0 + uu;
#pragma unroll
                    for (int nt = 0; nt < 2; nt++) {
                        int o = ng2 * 16 + nt * 8 + ((l & 3) << 1);
                        float2 x0 = *(const float2*)&xf_in[(size_t)pb * 32 + o];
                        float n0 = x0.x + c2[nt][half * 2 + 0];
                        float n1 = x0.y + c2[nt][half * 2 + 1];
                        *(float2*)&xf_out[(size_t)pb * 32 + o] = make_float2(n0, n1);
                        uint32_t gi = (pb << 5) + (uint32_t)(o >> 1);
                        xo[gi]      = pack2(bfhi(n0), bfhi(n1));
                        xo[gi + 16] = pack2(bflo(n0), bflo(n1));
                    }
                }
            }
        }
    }
}

// ---------------------------------------------------------------------------
extern "C" void kernel_launch(void* const* d_in, const int* in_sizes, int n_in,
                              void* d_out, int out_size) {
    const float* x    = (const float*)d_in[0];
    const float* xvec = (const float*)d_in[1];
    const float* fc0w = (const float*)d_in[2];
    const float* fc0b = (const float*)d_in[3];
    const float* fc1w = (const float*)d_in[4];
    const float* p0w  = (const float*)d_in[5];
    const float* p0b  = (const float*)d_in[6];
    const float* p1w  = (const float*)d_in[7];
    const float* p1b  = (const float*)d_in[8];
    const float* bptw = (const float*)d_in[9];
    const float* bptb = (const float*)d_in[10];

    cudaFuncSetAttribute(nca_step, cudaFuncAttributeMaxDynamicSharedMemorySize, SMEM_BYTES);

    prep1<<<289, 128>>>(fc0w, fc0b, p0w, p0b, p1w, p1b);
    prep2<<<196, 256>>>(fc1w);
    init_state<<<PLANE_ / 256, 256>>>(x, xvec, bptw, bptb);
    for (int s = 0; s < STEPS_; s++)
        nca_step<<<dim3(16, 8), 256, SMEM_BYTES>>>(s);
    final_out<<<PLANE_ / 256, 256>>>((float*)d_out);
}